// round 5
// baseline (speedup 1.0000x reference)
#include <cuda_runtime.h>
#include <cuda_fp16.h>
#include <math_constants.h>
#include <cstdint>

// Problem constants
#define K_CODES 8192
#define DIM     256
#define TLEN    2048
#define BATCH   16
#define NTOK    32768           // BATCH*TLEN

// Output layout (float32, concatenated in reference-return order)
#define OFF_ZQ    0ull
#define OFF_IDX   8388608ull
#define OFF_LOSS  8421376ull
#define OFF_NEMB  8421377ull
#define OFF_NCS   10518529ull
#define OFF_NEA   10526721ull
#define OFF_UTIL  12623873ull

#define MARGIN 0.03f

// Scratch (device globals; no allocation allowed). uint4 for 16B alignment.
__device__ float g_esq[K_CODES];
__device__ int   g_idx[NTOK];
__device__ float g_counts[K_CODES];
__device__ float g_sumemb[K_CODES * DIM];
__device__ float g_scal[4];   // [0]=loss partial sum, [1]=n
__device__ int   g_nfix;
__device__ int   g_fixlist[NTOK];
__device__ uint4 g_z1u[NTOK * DIM / 8];     // fp16 hi split of z, (token, dim)
__device__ uint4 g_z2u[NTOK * DIM / 8];     // fp16 lo split
__device__ uint4 g_e1u[K_CODES * DIM / 8];  // fp16 hi split of codebook, (code, dim)
__device__ uint4 g_e2u[K_CODES * DIM / 8];  // fp16 lo split

// ===========================================================================
// PTX helpers (plain sm_80+ features only — no tcgen05 on this toolchain)
// ===========================================================================
__device__ __forceinline__ uint32_t smem_to_u32(const void* smem_ptr) {
    uint32_t addr;
    asm("{ .reg .u64 tmp; cvta.to.shared.u64 tmp, %1; cvt.u32.u64 %0, tmp; }"
        : "=r"(addr) : "l"(smem_ptr));
    return addr;
}

#define CP_ASYNC16(dst, src) \
    asm volatile("cp.async.cg.shared.global [%0], [%1], 16;" :: "r"(dst), "l"(src) : "memory")
#define CP_COMMIT() asm volatile("cp.async.commit_group;" ::: "memory")
#define CP_WAIT1()  asm volatile("cp.async.wait_group 1;" ::: "memory")
#define CP_WAIT0()  asm volatile("cp.async.wait_group 0;" ::: "memory")

__device__ __forceinline__ void ldsm_x4(uint32_t* r, uint32_t addr) {
    asm volatile("ldmatrix.sync.aligned.m8n8.x4.shared.b16 {%0,%1,%2,%3}, [%4];"
        : "=r"(r[0]), "=r"(r[1]), "=r"(r[2]), "=r"(r[3]) : "r"(addr));
}

__device__ __forceinline__ void mma_16816(float* c, const uint32_t* a, const uint32_t* b) {
    asm volatile(
        "mma.sync.aligned.m16n8k16.row.col.f32.f16.f16.f32 "
        "{%0,%1,%2,%3}, {%4,%5,%6,%7}, {%8,%9}, {%0,%1,%2,%3};"
        : "+f"(c[0]), "+f"(c[1]), "+f"(c[2]), "+f"(c[3])
        : "r"(a[0]), "r"(a[1]), "r"(a[2]), "r"(a[3]), "r"(b[0]), "r"(b[1]));
}

// ===========================================================================
// Zero scratch accumulators (every launch)
// ===========================================================================
__global__ void k_init() {
    int gid = blockIdx.x * blockDim.x + threadIdx.x;
    if (gid < K_CODES * DIM / 4)
        ((float4*)g_sumemb)[gid] = make_float4(0.f, 0.f, 0.f, 0.f);
    if (gid < K_CODES) g_counts[gid] = 0.f;
    if (gid < 4) g_scal[gid] = 0.f;
    if (gid == 0) g_nfix = 0;
}

// ===========================================================================
// esq[k] = ||embedding[k]||^2   (one warp per code)
// ===========================================================================
__global__ void k_esq(const float* __restrict__ emb) {
    int warp = (blockIdx.x * blockDim.x + threadIdx.x) >> 5;
    int lane = threadIdx.x & 31;
    const float* row = emb + (size_t)warp * DIM;
    float s = 0.f;
#pragma unroll
    for (int q = 0; q < 8; q++) { float v = row[lane + q * 32]; s = fmaf(v, v, s); }
#pragma unroll
    for (int o = 16; o; o >>= 1) s += __shfl_xor_sync(0xFFFFFFFFu, s, o);
    if (lane == 0) g_esq[warp] = s;
}

// ===========================================================================
// z prep: (b, d, t) fp32 -> (token, dim) fp16 2-way split, transposed in smem.
// ===========================================================================
__global__ void k_prep_z(const float* __restrict__ z) {
    __shared__ float s[64][65];
    int blk = blockIdx.x;
    int tg = blk & 31, dg = (blk >> 5) & 3, b = blk >> 7;
    int tid = threadIdx.x;
    const float* zb = z + (size_t)b * DIM * TLEN;
#pragma unroll
    for (int l = 0; l < 16; l++) {
        int idx = tid + l * 256;           // 0..4095
        int d = idx >> 6, t = idx & 63;
        s[d][t] = zb[(size_t)(dg * 64 + d) * TLEN + tg * 64 + t];
    }
    __syncthreads();
    __half* z1 = (__half*)g_z1u;
    __half* z2 = (__half*)g_z2u;
#pragma unroll
    for (int l = 0; l < 16; l++) {
        int idx = tid + l * 256;
        int t = idx >> 6, d = idx & 63;
        float v = s[d][t];
        __half h1 = __float2half_rn(v);
        __half h2 = __float2half_rn(v - __half2float(h1));
        size_t off = (size_t)(b * 2048 + tg * 64 + t) * DIM + dg * 64 + d;
        z1[off] = h1;
        z2[off] = h2;
    }
}

// ===========================================================================
// Codebook prep: fp16 2-way split, same (code, dim) layout.
// ===========================================================================
__global__ void k_prep_e(const float* __restrict__ emb) {
    int gid = blockIdx.x * blockDim.x + threadIdx.x;   // float4 index < K*D/4
    float4 v = ((const float4*)emb)[gid];
    __half2* e1 = (__half2*)g_e1u;
    __half2* e2 = (__half2*)g_e2u;
    __half hx = __float2half_rn(v.x), hy = __float2half_rn(v.y);
    __half hz = __float2half_rn(v.z), hw = __float2half_rn(v.w);
    e1[gid * 2 + 0] = __halves2half2(hx, hy);
    e1[gid * 2 + 1] = __halves2half2(hz, hw);
    e2[gid * 2 + 0] = __halves2half2(__float2half_rn(v.x - __half2float(hx)),
                                     __float2half_rn(v.y - __half2float(hy)));
    e2[gid * 2 + 1] = __halves2half2(__float2half_rn(v.z - __half2float(hz)),
                                     __float2half_rn(v.w - __half2float(hw)));
}

// ===========================================================================
// Fused mma.sync distance GEMM + certified argmin.
// CTA: 128 tokens x 8192 codes. A (z1,z2; 128KB) resident in smem.
// B chunks double-buffered via cp.async. 3 products: z1e1 + z1e2 + z2e1.
// Tokens with top-2 gap < MARGIN go to a fix-list for fp32 R1-style rescan.
// ===========================================================================
#define A_OFF   0u        // 131072 = 2 splits x 64KB
#define B_OFF   131072u   // 2 stages x 32768
#define ESQ_OFF 196608u   // 32KB
#define SMEM_MMA (ESQ_OFF + K_CODES * 4)   // 229376

__device__ __forceinline__ void prefetchB(uint32_t bstage, int ci, int tid) {
    const int tile = ci >> 2, c = ci & 3;
    const __half* e1 = (const __half*)g_e1u;
    const __half* e2 = (const __half*)g_e2u;
#pragma unroll
    for (int l = 0; l < 8; l++) {
        int idx = tid + l * 256;           // 0..2047 16B segs
        int split = idx >> 10;
        int rem = idx & 1023;
        int row = rem >> 3;                // code row 0..127
        int seg = rem & 7;
        const __half* src = (split ? e2 : e1)
            + (size_t)(tile * 128 + row) * DIM + c * 64 + seg * 8;
        uint32_t dst = bstage + split * 16384 + row * 128 + ((seg ^ (row & 7)) * 16);
        CP_ASYNC16(dst, (const void*)src);
    }
    CP_COMMIT();
}

__device__ __forceinline__ void t2u(float& v1, int& i1, float& v2, int& i2,
                                    float d, int code) {
    if (d < v2) {
        if (d < v1) { v2 = v1; i2 = i1; v1 = d; i1 = code; }
        else        { v2 = d;  i2 = code; }
    }
}

__global__ void __launch_bounds__(256, 1)
k_argmin_mma(float* __restrict__ out_idx) {
    extern __shared__ __align__(128) char smem[];
    const uint32_t sb = smem_to_u32(smem);
    float* esq_s = (float*)(smem + ESQ_OFF);
    const int tid = threadIdx.x, lane = tid & 31, wid = tid >> 5;
    const int wm = wid & 3, wn = wid >> 2;
    const int tok0 = blockIdx.x * 128;

    // esq -> smem
    for (int i = tid; i < K_CODES; i += 256) esq_s[i] = g_esq[i];

    // A tiles (z1, z2) -> smem, swizzled (one group)
    {
        const __half* z1 = (const __half*)g_z1u;
        const __half* z2 = (const __half*)g_z2u;
#pragma unroll
        for (int l = 0; l < 32; l++) {
            int idx = tid + l * 256;       // 0..8191 16B segs
            int split = idx >> 12;
            int rem = idx & 4095;
            int row = rem >> 5;            // token row 0..127
            int seg = rem & 31;
            const __half* src = (split ? z2 : z1)
                + (size_t)(tok0 + row) * DIM + seg * 8;
            uint32_t dst = sb + A_OFF + split * 65536 + row * 512
                         + ((seg ^ (row & 7)) * 16);
            CP_ASYNC16(dst, (const void*)src);
        }
        CP_COMMIT();
    }
    prefetchB(sb + B_OFF, 0, tid);

    float acc[2][8][4];
#pragma unroll
    for (int f = 0; f < 2; f++)
#pragma unroll
        for (int g = 0; g < 8; g++)
#pragma unroll
            for (int q = 0; q < 4; q++) acc[f][g][q] = 0.f;

    float v1[4], v2[4];
    int   i1[4], i2[4];
#pragma unroll
    for (int r = 0; r < 4; r++) { v1[r] = CUDART_INF_F; v2[r] = CUDART_INF_F; i1[r] = 0; i2[r] = 0; }

    for (int ci = 0; ci < 256; ci++) {
        __syncthreads();   // all done reading the buffer about to be overwritten
        if (ci + 1 < 256) {
            prefetchB(sb + B_OFF + ((ci + 1) & 1) * 32768, ci + 1, tid);
            CP_WAIT1();
        } else {
            CP_WAIT0();
        }
        __syncthreads();   // chunk ci (and, first iter, the A tile) visible

        const uint32_t bb = sb + B_OFF + (ci & 1) * 32768;
        const int c = ci & 3;
#pragma unroll
        for (int kk = 0; kk < 4; kk++) {
            uint32_t a[2][2][4];
            const int arow0 = 32 * wm + (lane & 15);
            const int aseg = 2 * (4 * c + kk) + (lane >> 4);
#pragma unroll
            for (int s = 0; s < 2; s++)
#pragma unroll
                for (int f = 0; f < 2; f++) {
                    int r = arow0 + 16 * f;
                    uint32_t addr = sb + A_OFF + s * 65536 + r * 512
                                  + ((aseg ^ (r & 7)) * 16);
                    ldsm_x4(a[s][f], addr);
                }
            uint32_t bfr[2][8][2];
            const int bseg = 2 * kk + (lane >> 4);
#pragma unroll
            for (int s = 0; s < 2; s++)
#pragma unroll
                for (int ng = 0; ng < 4; ng++) {
                    int r = 64 * wn + 16 * ng + (lane & 15);
                    uint32_t addr = bb + s * 16384 + r * 128
                                  + ((bseg ^ (r & 7)) * 16);
                    uint32_t t4[4];
                    ldsm_x4(t4, addr);
                    bfr[s][2 * ng][0] = t4[0]; bfr[s][2 * ng + 1][0] = t4[1];
                    bfr[s][2 * ng][1] = t4[2]; bfr[s][2 * ng + 1][1] = t4[3];
                }
#pragma unroll
            for (int f = 0; f < 2; f++)
#pragma unroll
                for (int g = 0; g < 8; g++) {
                    mma_16816(acc[f][g], a[0][f], bfr[0][g]);   // z1*e1
                    mma_16816(acc[f][g], a[0][f], bfr[1][g]);   // z1*e2
                    mma_16816(acc[f][g], a[1][f], bfr[0][g]);   // z2*e1
                }
        }

        if (c == 3) {
            const int tile = ci >> 2;
#pragma unroll
            for (int f = 0; f < 2; f++)
#pragma unroll
                for (int g = 0; g < 8; g++) {
                    int col = tile * 128 + 64 * wn + 8 * g + (lane & 3) * 2;
                    float2 eq = *(const float2*)(esq_s + col);
                    float d0 = fmaf(-2.f, acc[f][g][0], eq.x);
                    float d1 = fmaf(-2.f, acc[f][g][1], eq.y);
                    float d2 = fmaf(-2.f, acc[f][g][2], eq.x);
                    float d3 = fmaf(-2.f, acc[f][g][3], eq.y);
                    t2u(v1[2*f], i1[2*f], v2[2*f], i2[2*f], d0, col);
                    t2u(v1[2*f], i1[2*f], v2[2*f], i2[2*f], d1, col + 1);
                    t2u(v1[2*f+1], i1[2*f+1], v2[2*f+1], i2[2*f+1], d2, col);
                    t2u(v1[2*f+1], i1[2*f+1], v2[2*f+1], i2[2*f+1], d3, col + 1);
                    acc[f][g][0] = 0.f; acc[f][g][1] = 0.f;
                    acc[f][g][2] = 0.f; acc[f][g][3] = 0.f;
                }
        }
    }

    // ---- cross-thread top-2 merge (8 contributors per token row) ----
    __syncthreads();
    float4* red = (float4*)(smem + B_OFF);    // [128][8]
#pragma unroll
    for (int f2 = 0; f2 < 4; f2++) {
        int row = 32 * wm + 16 * (f2 >> 1) + (lane >> 2) + 8 * (f2 & 1);
        int contrib = wn * 4 + (lane & 3);
        red[row * 8 + contrib] = make_float4(v1[f2], __int_as_float(i1[f2]),
                                             v2[f2], __int_as_float(i2[f2]));
    }
    __syncthreads();
    if (tid < 128) {
        float V1 = CUDART_INF_F, V2 = CUDART_INF_F;
        int I1 = 0, I2 = 0;
#pragma unroll 2
        for (int c8 = 0; c8 < 8; c8++) {
            float4 rec = red[tid * 8 + c8];
            float va = rec.x; int ia = __float_as_int(rec.y);
            float vb = rec.z; int ib = __float_as_int(rec.w);
            if (va < V1 || (va == V1 && ia < I1)) { V2 = V1; I2 = I1; V1 = va; I1 = ia; }
            else if (va < V2 || (va == V2 && ia < I2)) { V2 = va; I2 = ia; }
            if (vb < V1 || (vb == V1 && ib < I1)) { V2 = V1; I2 = I1; V1 = vb; I1 = ib; }
            else if (vb < V2 || (vb == V2 && ib < I2)) { V2 = vb; I2 = ib; }
        }
        int token = tok0 + tid;
        g_idx[token] = I1;                 // provisional
        out_idx[token] = (float)I1;
        if (V2 - V1 < MARGIN) {
            int slot = atomicAdd(&g_nfix, 1);
            g_fixlist[slot] = token;
        }
    }
}

// ===========================================================================
// Full fp32 rescan for contested tokens, bit-replicating the R1 kernel's
// arithmetic: ascending-d fmaf chain, dist = fmaf(-2, dot, esq), first-min.
// Grid-stride over the fix list; one block per token item.
// ===========================================================================
__global__ void k_rescore(const float* __restrict__ z,
                          const float* __restrict__ emb,
                          float* __restrict__ out_idx) {
    __shared__ float zcol[DIM];
    __shared__ float rv[256];
    __shared__ int   ri[256];
    int tid = threadIdx.x;
    int nfix = g_nfix;
    for (int item = blockIdx.x; item < nfix; item += gridDim.x) {
        int token = g_fixlist[item];
        int b = token >> 11, t = token & 2047;
        const float* zb = z + (size_t)b * DIM * TLEN + t;
        if (tid < DIM) zcol[tid] = zb[(size_t)tid * TLEN];
        __syncthreads();
        float bv = CUDART_INF_F;
        int   bi = 0;
        for (int k = tid; k < K_CODES; k += 256) {
            const float* er = emb + (size_t)k * DIM;
            float acc = 0.f;
#pragma unroll 8
            for (int d = 0; d < DIM; d++) acc = fmaf(zcol[d], er[d], acc);
            float dist = fmaf(-2.f, acc, g_esq[k]);
            if (dist < bv) { bv = dist; bi = k; }   // ascending k: first min
        }
        rv[tid] = bv; ri[tid] = bi;
        __syncthreads();
        for (int s = 128; s; s >>= 1) {
            if (tid < s) {
                float v = rv[tid + s]; int id = ri[tid + s];
                if (v < rv[tid] || (v == rv[tid] && id < ri[tid])) {
                    rv[tid] = v; ri[tid] = id;
                }
            }
            __syncthreads();
        }
        if (tid == 0) {
            g_idx[token] = ri[0];
            out_idx[token] = (float)ri[0];
        }
        __syncthreads();
    }
}

// ===========================================================================
// Fused counts/sum_embeddings scatter, z_q gather, commitment-loss partial.
// grid (NTOK/256, 4): y splits the d range into 4 chunks of 64.
// ===========================================================================
__global__ void k_scatter_gather(const float* __restrict__ z,
                                 const float* __restrict__ emb,
                                 float* __restrict__ out_zq) {
    int tid   = threadIdx.x;
    int tok0  = blockIdx.x * 256;
    int b     = tok0 >> 11;
    int tl    = (tok0 & 2047) + tid;
    int token = tok0 + tid;
    int idx   = g_idx[token];
    if (blockIdx.y == 0) atomicAdd(&g_counts[idx], 1.0f);

    int d0 = blockIdx.y * 64;
    const float* zb = z + (size_t)b * DIM * TLEN;
    float*       ob = out_zq + (size_t)b * DIM * TLEN;
    const float* er = emb + (size_t)idx * DIM;
    float* sr = g_sumemb + (size_t)idx * DIM;

    float lacc = 0.f;
#pragma unroll 8
    for (int dd = 0; dd < 64; dd++) {
        int d = d0 + dd;
        float zv = zb[(size_t)d * TLEN + tl];
        float ev = __ldg(er + d);
        ob[(size_t)d * TLEN + tl] = zv + (ev - zv);   // straight-through
        atomicAdd(sr + d, zv);
        float df = zv - ev;
        lacc = fmaf(df, df, lacc);
    }
#pragma unroll
    for (int o = 16; o; o >>= 1) lacc += __shfl_xor_sync(0xFFFFFFFFu, lacc, o);
    if ((tid & 31) == 0) atomicAdd(&g_scal[0], lacc);
}

// ===========================================================================
// Single block: new_cluster_size, n, utilization, loss.
// ===========================================================================
__global__ void k_reduce(const float* __restrict__ cs,
                         float* __restrict__ out_ncs,
                         float* __restrict__ out_loss,
                         float* __restrict__ out_util) {
    __shared__ float sn[256];
    __shared__ float sz[256];
    int tid = threadIdx.x;
    const float om = (float)(1.0 - 0.99);
    float nsum = 0.f, nz = 0.f;
    for (int k = tid; k < K_CODES; k += 256) {
        float c   = g_counts[k];
        float ncs = cs[k] * 0.99f + om * c;
        out_ncs[k] = ncs;
        nsum += ncs;
        nz += (c > 0.f) ? 1.f : 0.f;
    }
    sn[tid] = nsum; sz[tid] = nz;
    __syncthreads();
    for (int s = 128; s; s >>= 1) {
        if (tid < s) { sn[tid] += sn[tid + s]; sz[tid] += sz[tid + s]; }
        __syncthreads();
    }
    if (tid == 0) {
        g_scal[1] = sn[0];
        *out_loss = 1.0f * (g_scal[0] / (float)(NTOK * DIM));
        *out_util = sz[0] / (float)K_CODES;
    }
}

// ===========================================================================
// Elementwise EMA update.
// ===========================================================================
__global__ void k_update(const float* __restrict__ cs,
                         const float* __restrict__ ea,
                         float* __restrict__ out_nemb,
                         float* __restrict__ out_nea) {
    int gid = blockIdx.x * blockDim.x + threadIdx.x;
    int k = gid >> 8;
    const float om = (float)(1.0 - 0.99);
    float n   = g_scal[1];
    float ncs = cs[k] * 0.99f + om * g_counts[k];
    float smoothed = (ncs + 1e-5f) / (n + (float)(K_CODES * 1e-5)) * n;
    float nav = ea[gid] * 0.99f + om * g_sumemb[gid];
    out_nea[gid]  = nav;
    out_nemb[gid] = nav / smoothed;
}

// ===========================================================================
extern "C" void kernel_launch(void* const* d_in, const int* in_sizes, int n_in,
                              void* d_out, int out_size) {
    const float* z   = (const float*)d_in[0];   // (16, 256, 2048)
    const float* emb = (const float*)d_in[1];   // (8192, 256)
    const float* cs  = (const float*)d_in[2];   // (8192,)
    const float* ea  = (const float*)d_in[3];   // (8192, 256)
    float* out = (float*)d_out;

    float* o_zq   = out + OFF_ZQ;
    float* o_idx  = out + OFF_IDX;
    float* o_loss = out + OFF_LOSS;
    float* o_nemb = out + OFF_NEMB;
    float* o_ncs  = out + OFF_NCS;
    float* o_nea  = out + OFF_NEA;
    float* o_util = out + OFF_UTIL;

    cudaFuncSetAttribute(k_argmin_mma,
                         cudaFuncAttributeMaxDynamicSharedMemorySize, SMEM_MMA);

    k_init<<<2048, 256>>>();
    k_esq<<<K_CODES / 8, 256>>>(emb);
    k_prep_z<<<2048, 256>>>(z);
    k_prep_e<<<K_CODES * DIM / 4 / 256, 256>>>(emb);
    k_argmin_mma<<<NTOK / 128, 256, SMEM_MMA>>>(o_idx);
    k_rescore<<<64, 256>>>(z, emb, o_idx);
    dim3 sg_grid(NTOK / 256, 4);
    k_scatter_gather<<<sg_grid, 256>>>(z, emb, o_zq);
    k_reduce<<<1, 256>>>(cs, o_ncs, o_loss, o_util);
    k_update<<<K_CODES * DIM / 256, 256>>>(cs, ea, o_nemb, o_nea);
}

// round 6
// speedup vs baseline: 1.2317x; 1.2317x over previous
#include <cuda_runtime.h>
#include <cuda_fp16.h>
#include <math_constants.h>
#include <cstdint>

// Problem constants
#define K_CODES 8192
#define DIM     256
#define TLEN    2048
#define BATCH   16
#define NTOK    32768           // BATCH*TLEN

// Output layout (float32, concatenated in reference-return order)
#define OFF_ZQ    0ull
#define OFF_IDX   8388608ull
#define OFF_LOSS  8421376ull
#define OFF_NEMB  8421377ull
#define OFF_NCS   10518529ull
#define OFF_NEA   10526721ull
#define OFF_UTIL  12623873ull

#define MARGIN 0.15f

// Scratch (device globals; no allocation allowed). uint4 for 16B alignment.
__device__ float g_esq[K_CODES];
__device__ int   g_idx[NTOK];
__device__ float g_counts[K_CODES];
__device__ float g_sumemb[K_CODES * DIM];
__device__ float g_scal[4];   // [0]=loss partial sum, [1]=n
__device__ int   g_nfix;
__device__ int   g_fixlist[NTOK];
__device__ uint4 g_z1u[NTOK * DIM / 8];     // fp16 z, (token, dim)
__device__ uint4 g_e1u[K_CODES * DIM / 8];  // fp16 codebook, (code, dim)

// ===========================================================================
// PTX helpers (plain sm_80+ features — tcgen05 unavailable on compute_100)
// ===========================================================================
__device__ __forceinline__ uint32_t smem_to_u32(const void* smem_ptr) {
    uint32_t addr;
    asm("{ .reg .u64 tmp; cvta.to.shared.u64 tmp, %1; cvt.u32.u64 %0, tmp; }"
        : "=r"(addr) : "l"(smem_ptr));
    return addr;
}

#define CP_ASYNC16(dst, src) \
    asm volatile("cp.async.cg.shared.global [%0], [%1], 16;" :: "r"(dst), "l"(src) : "memory")
#define CP_COMMIT() asm volatile("cp.async.commit_group;" ::: "memory")
#define CP_WAIT1()  asm volatile("cp.async.wait_group 1;" ::: "memory")
#define CP_WAIT0()  asm volatile("cp.async.wait_group 0;" ::: "memory")

__device__ __forceinline__ void ldsm_x4(uint32_t* r, uint32_t addr) {
    asm volatile("ldmatrix.sync.aligned.m8n8.x4.shared.b16 {%0,%1,%2,%3}, [%4];"
        : "=r"(r[0]), "=r"(r[1]), "=r"(r[2]), "=r"(r[3]) : "r"(addr));
}

__device__ __forceinline__ void mma_16816(float* c, const uint32_t* a, const uint32_t* b) {
    asm volatile(
        "mma.sync.aligned.m16n8k16.row.col.f32.f16.f16.f32 "
        "{%0,%1,%2,%3}, {%4,%5,%6,%7}, {%8,%9}, {%0,%1,%2,%3};"
        : "+f"(c[0]), "+f"(c[1]), "+f"(c[2]), "+f"(c[3])
        : "r"(a[0]), "r"(a[1]), "r"(a[2]), "r"(a[3]), "r"(b[0]), "r"(b[1]));
}

// ===========================================================================
// Zero scratch accumulators (every launch)
// ===========================================================================
__global__ void k_init() {
    int gid = blockIdx.x * blockDim.x + threadIdx.x;
    if (gid < K_CODES * DIM / 4)
        ((float4*)g_sumemb)[gid] = make_float4(0.f, 0.f, 0.f, 0.f);
    if (gid < K_CODES) g_counts[gid] = 0.f;
    if (gid < 4) g_scal[gid] = 0.f;
    if (gid == 0) g_nfix = 0;
}

// ===========================================================================
// esq[k] = ||embedding[k]||^2   (one warp per code)
// ===========================================================================
__global__ void k_esq(const float* __restrict__ emb) {
    int warp = (blockIdx.x * blockDim.x + threadIdx.x) >> 5;
    int lane = threadIdx.x & 31;
    const float* row = emb + (size_t)warp * DIM;
    float s = 0.f;
#pragma unroll
    for (int q = 0; q < 8; q++) { float v = row[lane + q * 32]; s = fmaf(v, v, s); }
#pragma unroll
    for (int o = 16; o; o >>= 1) s += __shfl_xor_sync(0xFFFFFFFFu, s, o);
    if (lane == 0) g_esq[warp] = s;
}

// ===========================================================================
// z prep: (b, d, t) fp32 -> (token, dim) fp16, transposed in smem.
// ===========================================================================
__global__ void k_prep_z(const float* __restrict__ z) {
    __shared__ float s[64][65];
    int blk = blockIdx.x;
    int tg = blk & 31, dg = (blk >> 5) & 3, b = blk >> 7;
    int tid = threadIdx.x;
    const float* zb = z + (size_t)b * DIM * TLEN;
#pragma unroll
    for (int l = 0; l < 16; l++) {
        int idx = tid + l * 256;           // 0..4095
        int d = idx >> 6, t = idx & 63;
        s[d][t] = zb[(size_t)(dg * 64 + d) * TLEN + tg * 64 + t];
    }
    __syncthreads();
    __half* z1 = (__half*)g_z1u;
#pragma unroll
    for (int l = 0; l < 16; l++) {
        int idx = tid + l * 256;
        int t = idx >> 6, d = idx & 63;
        size_t off = (size_t)(b * 2048 + tg * 64 + t) * DIM + dg * 64 + d;
        z1[off] = __float2half_rn(s[d][t]);
    }
}

// ===========================================================================
// Codebook prep: fp16, (code, dim) layout.
// ===========================================================================
__global__ void k_prep_e(const float* __restrict__ emb) {
    int gid = blockIdx.x * blockDim.x + threadIdx.x;   // float4 index < K*D/4
    float4 v = ((const float4*)emb)[gid];
    __half2* e1 = (__half2*)g_e1u;
    e1[gid * 2 + 0] = __halves2half2(__float2half_rn(v.x), __float2half_rn(v.y));
    e1[gid * 2 + 1] = __halves2half2(__float2half_rn(v.z), __float2half_rn(v.w));
}

// ===========================================================================
// Single-product fp16 mma.sync screen GEMM + top-2 + margin gate.
// CTA: 128 tokens x 8192 codes. A (64KB) resident; B double-buffered 2x16KB.
// 8 warps 4m x 2n; warp tile 32x64. smem 96KB -> 2 CTAs/SM.
// Tokens with top-2 gap < MARGIN go to the fix-list for exact fp32 rescan.
// ===========================================================================
#define A_OFF   0u        // 65536 = 128 rows x 512B
#define B_OFF   65536u    // 2 stages x 16384
#define SMEM_MMA (B_OFF + 2u * 16384u)   // 98304

__device__ __forceinline__ void prefetchB(uint32_t bstage, int ci, int tid) {
    const int tile = ci >> 2, c = ci & 3;
    const __half* e1 = (const __half*)g_e1u;
#pragma unroll
    for (int l = 0; l < 4; l++) {
        int idx = tid + l * 256;           // 0..1023 16B segs
        int row = idx >> 3;                // code row 0..127
        int seg = idx & 7;
        const __half* src = e1 + (size_t)(tile * 128 + row) * DIM + c * 64 + seg * 8;
        uint32_t dst = bstage + row * 128 + ((seg ^ (row & 7)) * 16);
        CP_ASYNC16(dst, (const void*)src);
    }
    CP_COMMIT();
}

__device__ __forceinline__ void t2u(float& v1, int& i1, float& v2, int& i2,
                                    float d, int code) {
    if (d < v2) {
        if (d < v1) { v2 = v1; i2 = i1; v1 = d; i1 = code; }
        else        { v2 = d;  i2 = code; }
    }
}

__global__ void __launch_bounds__(256, 2)
k_argmin_mma(float* __restrict__ out_idx) {
    extern __shared__ __align__(128) char smem[];
    const uint32_t sb = smem_to_u32(smem);
    const int tid = threadIdx.x, lane = tid & 31, wid = tid >> 5;
    const int wm = wid & 3, wn = wid >> 2;
    const int tok0 = blockIdx.x * 128;

    // A tile (fp16 z, 128 tokens x 256 dims) -> smem, swizzled
    {
        const __half* z1 = (const __half*)g_z1u;
#pragma unroll
        for (int l = 0; l < 16; l++) {
            int idx = tid + l * 256;       // 0..4095 16B segs
            int row = idx >> 5;            // token row 0..127
            int seg = idx & 31;
            const __half* src = z1 + (size_t)(tok0 + row) * DIM + seg * 8;
            uint32_t dst = sb + A_OFF + row * 512 + ((seg ^ (row & 7)) * 16);
            CP_ASYNC16(dst, (const void*)src);
        }
        CP_COMMIT();
    }
    prefetchB(sb + B_OFF, 0, tid);

    float acc[2][8][4];
#pragma unroll
    for (int f = 0; f < 2; f++)
#pragma unroll
        for (int g = 0; g < 8; g++)
#pragma unroll
            for (int q = 0; q < 4; q++) acc[f][g][q] = 0.f;

    float v1[4], v2[4];
    int   i1[4], i2[4];
#pragma unroll
    for (int r = 0; r < 4; r++) { v1[r] = CUDART_INF_F; v2[r] = CUDART_INF_F; i1[r] = 0; i2[r] = 0; }

    for (int ci = 0; ci < 256; ci++) {
        __syncthreads();   // all done reading the buffer about to be overwritten
        if (ci + 1 < 256) {
            prefetchB(sb + B_OFF + ((ci + 1) & 1) * 16384, ci + 1, tid);
            CP_WAIT1();
        } else {
            CP_WAIT0();
        }
        __syncthreads();   // chunk ci (and, first iter, the A tile) visible

        const uint32_t bb = sb + B_OFF + (ci & 1) * 16384;
        const int c = ci & 3;
#pragma unroll
        for (int kk = 0; kk < 4; kk++) {
            uint32_t a[2][4];
            const int arow0 = 32 * wm + (lane & 15);
            const int aseg = 2 * (4 * c + kk) + (lane >> 4);
#pragma unroll
            for (int f = 0; f < 2; f++) {
                int r = arow0 + 16 * f;
                uint32_t addr = sb + A_OFF + r * 512 + ((aseg ^ (r & 7)) * 16);
                ldsm_x4(a[f], addr);
            }
            uint32_t bfr[8][2];
            const int bseg = 2 * kk + (lane >> 4);
#pragma unroll
            for (int ng = 0; ng < 4; ng++) {
                int r = 64 * wn + 16 * ng + (lane & 15);
                uint32_t addr = bb + r * 128 + ((bseg ^ (r & 7)) * 16);
                uint32_t t4[4];
                ldsm_x4(t4, addr);
                bfr[2 * ng][0] = t4[0]; bfr[2 * ng + 1][0] = t4[1];
                bfr[2 * ng][1] = t4[2]; bfr[2 * ng + 1][1] = t4[3];
            }
#pragma unroll
            for (int f = 0; f < 2; f++)
#pragma unroll
                for (int g = 0; g < 8; g++)
                    mma_16816(acc[f][g], a[f], bfr[g]);
        }

        if (c == 3) {
            const int tile = ci >> 2;
#pragma unroll
            for (int f = 0; f < 2; f++)
#pragma unroll
                for (int g = 0; g < 8; g++) {
                    int col = tile * 128 + 64 * wn + 8 * g + (lane & 3) * 2;
                    float2 eq = __ldg((const float2*)(g_esq + col));
                    float d0 = fmaf(-2.f, acc[f][g][0], eq.x);
                    float d1 = fmaf(-2.f, acc[f][g][1], eq.y);
                    float d2 = fmaf(-2.f, acc[f][g][2], eq.x);
                    float d3 = fmaf(-2.f, acc[f][g][3], eq.y);
                    t2u(v1[2*f], i1[2*f], v2[2*f], i2[2*f], d0, col);
                    t2u(v1[2*f], i1[2*f], v2[2*f], i2[2*f], d1, col + 1);
                    t2u(v1[2*f+1], i1[2*f+1], v2[2*f+1], i2[2*f+1], d2, col);
                    t2u(v1[2*f+1], i1[2*f+1], v2[2*f+1], i2[2*f+1], d3, col + 1);
                    acc[f][g][0] = 0.f; acc[f][g][1] = 0.f;
                    acc[f][g][2] = 0.f; acc[f][g][3] = 0.f;
                }
        }
    }

    // ---- cross-thread top-2 merge (8 contributors per token row) ----
    __syncthreads();
    float4* red = (float4*)(smem + B_OFF);    // [128][8], reuses B stages
#pragma unroll
    for (int f2 = 0; f2 < 4; f2++) {
        int row = 32 * wm + 16 * (f2 >> 1) + (lane >> 2) + 8 * (f2 & 1);
        int contrib = wn * 4 + (lane & 3);
        red[row * 8 + contrib] = make_float4(v1[f2], __int_as_float(i1[f2]),
                                             v2[f2], __int_as_float(i2[f2]));
    }
    __syncthreads();
    if (tid < 128) {
        float V1 = CUDART_INF_F, V2 = CUDART_INF_F;
        int I1 = 0, I2 = 0;
#pragma unroll 2
        for (int c8 = 0; c8 < 8; c8++) {
            float4 rec = red[tid * 8 + c8];
            float va = rec.x; int ia = __float_as_int(rec.y);
            float vb = rec.z; int ib = __float_as_int(rec.w);
            if (va < V1 || (va == V1 && ia < I1)) { V2 = V1; I2 = I1; V1 = va; I1 = ia; }
            else if (va < V2 || (va == V2 && ia < I2)) { V2 = va; I2 = ia; }
            if (vb < V1 || (vb == V1 && ib < I1)) { V2 = V1; I2 = I1; V1 = vb; I1 = ib; }
            else if (vb < V2 || (vb == V2 && ib < I2)) { V2 = vb; I2 = ib; }
        }
        int token = tok0 + tid;
        g_idx[token] = I1;                 // provisional
        out_idx[token] = (float)I1;
        if (V2 - V1 < MARGIN) {
            int slot = atomicAdd(&g_nfix, 1);
            g_fixlist[slot] = token;
        }
    }
}

// ===========================================================================
// Exact fp32 rescan for contested tokens, replicating the reference-matching
// R1 arithmetic: ascending-d fmaf chain, dist = esq - 2*dot, first-min.
// 4 tokens per block share the codebook scan (4x L2 traffic amortization).
// ===========================================================================
__global__ void k_rescore(const float* __restrict__ z,
                          const float* __restrict__ emb,
                          float* __restrict__ out_idx) {
    __shared__ float zcol[4][DIM];
    __shared__ float rv[256];
    __shared__ int   ri[256];
    int tid = threadIdx.x;
    int nfix = g_nfix;
    for (int g0 = blockIdx.x * 4; g0 < nfix; g0 += gridDim.x * 4) {
        int cnt = min(4, nfix - g0);
        if (tid < DIM) {
#pragma unroll
            for (int t = 0; t < 4; t++) {
                if (t < cnt) {
                    int token = g_fixlist[g0 + t];
                    int b = token >> 11, tt = token & 2047;
                    zcol[t][tid] = z[(size_t)b * DIM * TLEN + (size_t)tid * TLEN + tt];
                } else {
                    zcol[t][tid] = 0.f;
                }
            }
        }
        __syncthreads();
        float bv[4]; int bi[4];
#pragma unroll
        for (int t = 0; t < 4; t++) { bv[t] = CUDART_INF_F; bi[t] = 0; }
        for (int k = tid; k < K_CODES; k += 256) {
            const float* er = emb + (size_t)k * DIM;
            float a0 = 0.f, a1 = 0.f, a2 = 0.f, a3 = 0.f;
#pragma unroll 8
            for (int d = 0; d < DIM; d++) {
                float ev = er[d];
                a0 = fmaf(zcol[0][d], ev, a0);
                a1 = fmaf(zcol[1][d], ev, a1);
                a2 = fmaf(zcol[2][d], ev, a2);
                a3 = fmaf(zcol[3][d], ev, a3);
            }
            float eq = g_esq[k];
            float d0 = eq - 2.0f * a0;
            float d1 = eq - 2.0f * a1;
            float d2 = eq - 2.0f * a2;
            float d3 = eq - 2.0f * a3;
            if (d0 < bv[0]) { bv[0] = d0; bi[0] = k; }   // ascending k: first min
            if (d1 < bv[1]) { bv[1] = d1; bi[1] = k; }
            if (d2 < bv[2]) { bv[2] = d2; bi[2] = k; }
            if (d3 < bv[3]) { bv[3] = d3; bi[3] = k; }
        }
        for (int t = 0; t < cnt; t++) {
            rv[tid] = bv[t]; ri[tid] = bi[t];
            __syncthreads();
            for (int s = 128; s; s >>= 1) {
                if (tid < s) {
                    float v = rv[tid + s]; int id = ri[tid + s];
                    if (v < rv[tid] || (v == rv[tid] && id < ri[tid])) {
                        rv[tid] = v; ri[tid] = id;
                    }
                }
                __syncthreads();
            }
            if (tid == 0) {
                int token = g_fixlist[g0 + t];
                g_idx[token] = ri[0];
                out_idx[token] = (float)ri[0];
            }
            __syncthreads();
        }
        __syncthreads();
    }
}

// ===========================================================================
// Fused counts/sum_embeddings scatter, z_q gather, commitment-loss partial.
// grid (NTOK/256, 4): y splits the d range into 4 chunks of 64.
// ===========================================================================
__global__ void k_scatter_gather(const float* __restrict__ z,
                                 const float* __restrict__ emb,
                                 float* __restrict__ out_zq) {
    int tid   = threadIdx.x;
    int tok0  = blockIdx.x * 256;
    int b     = tok0 >> 11;
    int tl    = (tok0 & 2047) + tid;
    int token = tok0 + tid;
    int idx   = g_idx[token];
    if (blockIdx.y == 0) atomicAdd(&g_counts[idx], 1.0f);

    int d0 = blockIdx.y * 64;
    const float* zb = z + (size_t)b * DIM * TLEN;
    float*       ob = out_zq + (size_t)b * DIM * TLEN;
    const float* er = emb + (size_t)idx * DIM;
    float* sr = g_sumemb + (size_t)idx * DIM;

    float lacc = 0.f;
#pragma unroll 8
    for (int dd = 0; dd < 64; dd++) {
        int d = d0 + dd;
        float zv = zb[(size_t)d * TLEN + tl];
        float ev = __ldg(er + d);
        ob[(size_t)d * TLEN + tl] = zv + (ev - zv);   // straight-through
        atomicAdd(sr + d, zv);
        float df = zv - ev;
        lacc = fmaf(df, df, lacc);
    }
#pragma unroll
    for (int o = 16; o; o >>= 1) lacc += __shfl_xor_sync(0xFFFFFFFFu, lacc, o);
    if ((tid & 31) == 0) atomicAdd(&g_scal[0], lacc);
}

// ===========================================================================
// Single block: new_cluster_size, n, utilization, loss.
// ===========================================================================
__global__ void k_reduce(const float* __restrict__ cs,
                         float* __restrict__ out_ncs,
                         float* __restrict__ out_loss,
                         float* __restrict__ out_util) {
    __shared__ float sn[256];
    __shared__ float sz[256];
    int tid = threadIdx.x;
    const float om = (float)(1.0 - 0.99);
    float nsum = 0.f, nz = 0.f;
    for (int k = tid; k < K_CODES; k += 256) {
        float c   = g_counts[k];
        float ncs = cs[k] * 0.99f + om * c;
        out_ncs[k] = ncs;
        nsum += ncs;
        nz += (c > 0.f) ? 1.f : 0.f;
    }
    sn[tid] = nsum; sz[tid] = nz;
    __syncthreads();
    for (int s = 128; s; s >>= 1) {
        if (tid < s) { sn[tid] += sn[tid + s]; sz[tid] += sz[tid + s]; }
        __syncthreads();
    }
    if (tid == 0) {
        g_scal[1] = sn[0];
        *out_loss = 1.0f * (g_scal[0] / (float)(NTOK * DIM));
        *out_util = sz[0] / (float)K_CODES;
    }
}

// ===========================================================================
// Elementwise EMA update.
// ===========================================================================
__global__ void k_update(const float* __restrict__ cs,
                         const float* __restrict__ ea,
                         float* __restrict__ out_nemb,
                         float* __restrict__ out_nea) {
    int gid = blockIdx.x * blockDim.x + threadIdx.x;
    int k = gid >> 8;
    const float om = (float)(1.0 - 0.99);
    float n   = g_scal[1];
    float ncs = cs[k] * 0.99f + om * g_counts[k];
    float smoothed = (ncs + 1e-5f) / (n + (float)(K_CODES * 1e-5)) * n;
    float nav = ea[gid] * 0.99f + om * g_sumemb[gid];
    out_nea[gid]  = nav;
    out_nemb[gid] = nav / smoothed;
}

// ===========================================================================
extern "C" void kernel_launch(void* const* d_in, const int* in_sizes, int n_in,
                              void* d_out, int out_size) {
    const float* z   = (const float*)d_in[0];   // (16, 256, 2048)
    const float* emb = (const float*)d_in[1];   // (8192, 256)
    const float* cs  = (const float*)d_in[2];   // (8192,)
    const float* ea  = (const float*)d_in[3];   // (8192, 256)
    float* out = (float*)d_out;

    float* o_zq   = out + OFF_ZQ;
    float* o_idx  = out + OFF_IDX;
    float* o_loss = out + OFF_LOSS;
    float* o_nemb = out + OFF_NEMB;
    float* o_ncs  = out + OFF_NCS;
    float* o_nea  = out + OFF_NEA;
    float* o_util = out + OFF_UTIL;

    cudaFuncSetAttribute(k_argmin_mma,
                         cudaFuncAttributeMaxDynamicSharedMemorySize, SMEM_MMA);

    k_init<<<2048, 256>>>();
    k_esq<<<K_CODES / 8, 256>>>(emb);
    k_prep_z<<<2048, 256>>>(z);
    k_prep_e<<<K_CODES * DIM / 4 / 256, 256>>>(emb);
    k_argmin_mma<<<NTOK / 128, 256, SMEM_MMA>>>(o_idx);
    k_rescore<<<128, 256>>>(z, emb, o_idx);
    dim3 sg_grid(NTOK / 256, 4);
    k_scatter_gather<<<sg_grid, 256>>>(z, emb, o_zq);
    k_reduce<<<1, 256>>>(cs, o_ncs, o_loss, o_util);
    k_update<<<K_CODES * DIM / 256, 256>>>(cs, ea, o_nemb, o_nea);
}